// round 1
// baseline (speedup 1.0000x reference)
#include <cuda_runtime.h>

#define GRIDL 256
#define CELLS (130 * 256 * 256)   // coords reach 129 = 127 + tap 2
#define NMAX  262144

// Dense voxel grid: head[cell] = point_index+1 (0 = empty), chained via g_next
__device__ int g_head[CELLS];
__device__ int g_next[NMAX];

__global__ void init_head() {
    int stride = gridDim.x * blockDim.x;
    for (int i = blockIdx.x * blockDim.x + threadIdx.x; i < CELLS; i += stride)
        g_head[i] = 0;
}

__global__ void build_chains(const int* __restrict__ in_pos, int N) {
    int n = blockIdx.x * blockDim.x + threadIdx.x;
    if (n >= N) return;
    int x = in_pos[3 * n + 0];
    int y = in_pos[3 * n + 1];
    int z = in_pos[3 * n + 2];
    int lid = (x * GRIDL + y) * GRIDL + z;
    int old = atomicExch(&g_head[lid], n + 1);
    g_next[n] = old;
}

// Shared layout: WT (transposed, padded) 27*32*36 floats, then per-warp acc 16*32*32
#define WT_STRIDE 36
#define WT_TAP    (32 * WT_STRIDE)          // 1152 floats per tap
#define SM_WT     (27 * WT_TAP)             // 31104 floats
#define SM_ACC    (16 * 1024)               // 16384 floats
#define SMEM_BYTES ((SM_WT + SM_ACC) * 4)   // 189952 bytes

__global__ __launch_bounds__(512, 1)
void gather_conv(const float* __restrict__ feat,
                 const int*   __restrict__ out_pos,
                 const float* __restrict__ W,
                 float*       __restrict__ out,
                 int M) {
    extern __shared__ float sm[];
    float* WT  = sm;
    float* acc = sm + SM_WT;

    int tid = threadIdx.x;

    // Stage W transposed+padded into smem: WT[k][f][c], row stride 36 floats (144B)
    for (int i = tid; i < 27 * 1024; i += 512) {
        int k = i >> 10;
        int rem = i & 1023;
        int c = rem >> 5;
        int f = rem & 31;
        WT[k * WT_TAP + f * WT_STRIDE + c] = W[i];
    }

    int warp = tid >> 5;
    int lane = tid & 31;
    float* accW = acc + warp * 1024;   // [32 rows][32 f]

    // zero per-warp accumulators (lane = feature column)
    #pragma unroll
    for (int r = 0; r < 32; r++) accW[r * 32 + lane] = 0.0f;
    __syncthreads();

    int rowBase = blockIdx.x * 512 + warp * 32;
    int myRow = rowBase + lane;
    bool myValid = myRow < M;
    int myLid = 0;
    if (myValid) {
        int x = out_pos[3 * myRow + 0];
        int y = out_pos[3 * myRow + 1];
        int z = out_pos[3 * myRow + 2];
        myLid = (x * GRIDL + y) * GRIDL + z;
    }

    for (int k = 0; k < 27; k++) {
        int di = k / 9;
        int rem9 = k - di * 9;
        int dj = rem9 / 3;
        int dk = rem9 - dj * 3;
        int cell = myLid + di * 65536 + dj * 256 + dk;

        int head = myValid ? __ldg(&g_head[cell]) : 0;
        unsigned mask = __ballot_sync(0xffffffffu, head != 0);
        if (!mask) continue;

        // hoist tap-k weight column for this lane's feature into registers
        const float* wt = WT + k * WT_TAP + lane * WT_STRIDE;
        float4 w0 = *(const float4*)(wt + 0);
        float4 w1 = *(const float4*)(wt + 4);
        float4 w2 = *(const float4*)(wt + 8);
        float4 w3 = *(const float4*)(wt + 12);
        float4 w4 = *(const float4*)(wt + 16);
        float4 w5 = *(const float4*)(wt + 20);
        float4 w6 = *(const float4*)(wt + 24);
        float4 w7 = *(const float4*)(wt + 28);

        while (mask) {
            int r = __ffs(mask) - 1;
            mask &= mask - 1;
            int p = __shfl_sync(0xffffffffu, head, r);
            float a = accW[r * 32 + lane];
            do {
                int n = p - 1;
                const float4* f4 = (const float4*)(feat + (size_t)n * 32);
                float4 v;
                v = __ldg(f4 + 0); a = fmaf(v.x, w0.x, a); a = fmaf(v.y, w0.y, a); a = fmaf(v.z, w0.z, a); a = fmaf(v.w, w0.w, a);
                v = __ldg(f4 + 1); a = fmaf(v.x, w1.x, a); a = fmaf(v.y, w1.y, a); a = fmaf(v.z, w1.z, a); a = fmaf(v.w, w1.w, a);
                v = __ldg(f4 + 2); a = fmaf(v.x, w2.x, a); a = fmaf(v.y, w2.y, a); a = fmaf(v.z, w2.z, a); a = fmaf(v.w, w2.w, a);
                v = __ldg(f4 + 3); a = fmaf(v.x, w3.x, a); a = fmaf(v.y, w3.y, a); a = fmaf(v.z, w3.z, a); a = fmaf(v.w, w3.w, a);
                v = __ldg(f4 + 4); a = fmaf(v.x, w4.x, a); a = fmaf(v.y, w4.y, a); a = fmaf(v.z, w4.z, a); a = fmaf(v.w, w4.w, a);
                v = __ldg(f4 + 5); a = fmaf(v.x, w5.x, a); a = fmaf(v.y, w5.y, a); a = fmaf(v.z, w5.z, a); a = fmaf(v.w, w5.w, a);
                v = __ldg(f4 + 6); a = fmaf(v.x, w6.x, a); a = fmaf(v.y, w6.y, a); a = fmaf(v.z, w6.z, a); a = fmaf(v.w, w6.w, a);
                v = __ldg(f4 + 7); a = fmaf(v.x, w7.x, a); a = fmaf(v.y, w7.y, a); a = fmaf(v.z, w7.z, a); a = fmaf(v.w, w7.w, a);
                p = __ldg(&g_next[n]);
            } while (p);
            accW[r * 32 + lane] = a;
        }
    }

    // write results (coalesced: 128B per row)
    #pragma unroll
    for (int r = 0; r < 32; r++) {
        int row = rowBase + r;
        if (row < M) out[row * 32 + lane] = accW[r * 32 + lane];
    }
}

extern "C" void kernel_launch(void* const* d_in, const int* in_sizes, int n_in,
                              void* d_out, int out_size) {
    const float* feat    = (const float*)d_in[0];
    const int*   in_pos  = (const int*)d_in[1];
    const int*   out_pos = (const int*)d_in[2];
    const float* W       = (const float*)d_in[3];
    float* out = (float*)d_out;

    int N = in_sizes[0] / 32;
    int M = in_sizes[2] / 3;

    cudaFuncSetAttribute(gather_conv, cudaFuncAttributeMaxDynamicSharedMemorySize, SMEM_BYTES);

    init_head<<<4096, 256>>>();
    build_chains<<<(N + 255) / 256, 256>>>(in_pos, N);
    gather_conv<<<(M + 511) / 512, 512, SMEM_BYTES>>>(feat, out_pos, W, out, M);
}